// round 1
// baseline (speedup 1.0000x reference)
#include <cuda_runtime.h>
#include <cstdint>

// Problem constants
#define BSZ 2
#define SEQ 8192
#define FD  512
#define NH  8
#define HD  64
#define NB  64          // SEQ / 128
#define MROWS (BSZ*SEQ) // 16384

// Scratch (allocation-free rule -> __device__ globals). Each 32 MB.
__device__ float g_q[(size_t)BSZ*NH*SEQ*HD];
__device__ float g_k[(size_t)BSZ*NH*SEQ*HD];
__device__ float g_v[(size_t)BSZ*NH*SEQ*HD];
__device__ float g_o[(size_t)BSZ*SEQ*NH*HD]; // [B,S,H,D]

// ---------------------------------------------------------------------------
// Tiled fp32 GEMM core: C[128x128] tile, BK=32, 256 threads, 8x8 micro-tile.
// A: [M,512] row-major. W: [512,512] row-major.
// ---------------------------------------------------------------------------
#define BKK 32

__device__ __forceinline__ void gemm_tile_body(
    const float* __restrict__ A, const float* __restrict__ W,
    int m0, int n0, float acc[8][8],
    float As[BKK][132], float Bs[BKK][128])
{
    const int tid = threadIdx.x;
    const int tx = tid & 15;
    const int ty = tid >> 4;

    for (int kt = 0; kt < FD; kt += BKK) {
        // Load A tile: 128 rows x 32 cols (1024 float4 / 256 thr = 4 each)
#pragma unroll
        for (int i = 0; i < 4; i++) {
            int id  = i * 256 + tid;
            int row = id >> 3;            // 0..127
            int cg  = (id & 7) << 2;      // 0,4,...,28
            float4 a = *(const float4*)(A + (size_t)(m0 + row) * FD + kt + cg);
            As[cg + 0][row] = a.x;
            As[cg + 1][row] = a.y;
            As[cg + 2][row] = a.z;
            As[cg + 3][row] = a.w;
        }
        // Load B tile: 32 rows x 128 cols
#pragma unroll
        for (int i = 0; i < 4; i++) {
            int id  = i * 256 + tid;
            int row = id >> 5;            // 0..31
            int c4  = (id & 31) << 2;     // 0..124
            *(float4*)&Bs[row][c4] =
                *(const float4*)(W + (size_t)(kt + row) * FD + n0 + c4);
        }
        __syncthreads();

#pragma unroll
        for (int k = 0; k < BKK; k++) {
            float a[8], b[8];
            *(float4*)&a[0] = *(const float4*)&As[k][ty * 8];
            *(float4*)&a[4] = *(const float4*)&As[k][ty * 8 + 4];
            *(float4*)&b[0] = *(const float4*)&Bs[k][tx * 8];
            *(float4*)&b[4] = *(const float4*)&Bs[k][tx * 8 + 4];
#pragma unroll
            for (int i = 0; i < 8; i++)
#pragma unroll
                for (int j = 0; j < 8; j++)
                    acc[i][j] += a[i] * b[j];
        }
        __syncthreads();
    }
}

// ---------------------------------------------------------------------------
// Kernel 1: QKV projection. grid = (4, 128, 3); z selects q/k/v.
// Output scattered to [B,H,S,D] layout in g_q / g_k / g_v.
// ---------------------------------------------------------------------------
__global__ void __launch_bounds__(256, 2) qkv_kernel(
    const float* __restrict__ Aq, const float* __restrict__ Akv,
    const float* __restrict__ Wq, const float* __restrict__ Wk,
    const float* __restrict__ Wv,
    const float* __restrict__ bq, const float* __restrict__ bk,
    const float* __restrict__ bv)
{
    __shared__ float As[BKK][132];
    __shared__ float Bs[BKK][128];

    const int z = blockIdx.z;
    const float* A    = (z == 0) ? Aq : Akv;
    const float* W    = (z == 0) ? Wq : (z == 1 ? Wk : Wv);
    const float* bias = (z == 0) ? bq : (z == 1 ? bk : bv);
    float* O          = (z == 0) ? g_q : (z == 1 ? g_k : g_v);

    const int n0 = blockIdx.x * 128;
    const int m0 = blockIdx.y * 128;

    float acc[8][8];
#pragma unroll
    for (int i = 0; i < 8; i++)
#pragma unroll
        for (int j = 0; j < 8; j++) acc[i][j] = 0.f;

    gemm_tile_body(A, W, m0, n0, acc, As, Bs);

    const int tx = threadIdx.x & 15;
    const int ty = threadIdx.x >> 4;
    const int col = n0 + tx * 8;       // 8 cols never cross a 64 boundary
    const int h = col >> 6;
    const int db = col & 63;
    float bb[8];
#pragma unroll
    for (int j = 0; j < 8; j++) bb[j] = bias[col + j];

#pragma unroll
    for (int i = 0; i < 8; i++) {
        int m = m0 + ty * 8 + i;
        int b = m >> 13;               // / SEQ
        int s = m & (SEQ - 1);
        float* op = O + (((size_t)(b * NH + h)) * SEQ + s) * HD + db;
        float4 v0 = make_float4(acc[i][0] + bb[0], acc[i][1] + bb[1],
                                acc[i][2] + bb[2], acc[i][3] + bb[3]);
        float4 v1 = make_float4(acc[i][4] + bb[4], acc[i][5] + bb[5],
                                acc[i][6] + bb[6], acc[i][7] + bb[7]);
        *(float4*)(op + 0) = v0;
        *(float4*)(op + 4) = v1;
    }
}

// ---------------------------------------------------------------------------
// Kernel 2: banded local attention.
// grid = (NB, NH, BSZ), 128 threads, one query row per thread.
// K/V staged through smem in 64-key chunks (32 KB static smem total).
// Scores are tiny (|s| < ~2), so single-pass exp without max-subtraction is
// numerically identical to the reference softmax.
// ---------------------------------------------------------------------------
__global__ void __launch_bounds__(128, 3) attn_kernel()
{
    __shared__ float sK[64 * 64];
    __shared__ float sV[64 * 64];

    const int n = blockIdx.x, h = blockIdx.y, b = blockIdx.z;
    const int qi = threadIdx.x;
    const size_t hb = ((size_t)(b * NH + h)) * SEQ;

    float q[64];
    {
        const float4* qrow = (const float4*)(g_q + (hb + (size_t)n * 128 + qi) * HD);
#pragma unroll
        for (int i = 0; i < 16; i++) ((float4*)q)[i] = qrow[i];
    }
    float acc[64];
#pragma unroll
    for (int i = 0; i < 64; i++) acc[i] = 0.f;
    float l = 0.f;

    for (int kb = 0; kb < 3; kb++) {
        const int kn = n - 1 + kb;
        if (kn < 0 || kn >= NB) continue;     // uniform across block
        const size_t kbase = (hb + (size_t)kn * 128) * HD;

        for (int c = 0; c < 2; c++) {
            // cooperative load of 64 K rows + 64 V rows
            {
                const int r = qi >> 1;
                const int half = (qi & 1) * 8;   // in float4 units
                const float4* kg = (const float4*)(g_k + kbase + (size_t)(c * 64 + r) * HD) + half;
                const float4* vg = (const float4*)(g_v + kbase + (size_t)(c * 64 + r) * HD) + half;
                float4* ks = (float4*)(sK + r * 64) + half;
                float4* vs = (float4*)(sV + r * 64) + half;
#pragma unroll
                for (int i = 0; i < 8; i++) { ks[i] = kg[i]; vs[i] = vg[i]; }
            }
            __syncthreads();

#pragma unroll 2
            for (int jj = 0; jj < 64; jj++) {
                const int j = c * 64 + jj;
                float s0 = 0.f, s1 = 0.f, s2 = 0.f, s3 = 0.f;
                const float4* kj = (const float4*)(sK + jj * 64);
#pragma unroll
                for (int i = 0; i < 16; i++) {
                    float4 kk = kj[i];
                    s0 += q[4 * i + 0] * kk.x;
                    s1 += q[4 * i + 1] * kk.y;
                    s2 += q[4 * i + 2] * kk.z;
                    s3 += q[4 * i + 3] * kk.w;
                }
                const float s = (s0 + s1) + (s2 + s3);
                // band mask: kb=0 -> j>=qi ; kb=1 -> always ; kb=2 -> j<qi
                const bool valid = (kb == 1) || (kb == 0 ? (j >= qi) : (j < qi));
                const float p = valid ? __expf(s * 0.125f) : 0.f;
                l += p;
                const float4* vj = (const float4*)(sV + jj * 64);
#pragma unroll
                for (int i = 0; i < 16; i++) {
                    float4 vv = vj[i];
                    acc[4 * i + 0] += p * vv.x;
                    acc[4 * i + 1] += p * vv.y;
                    acc[4 * i + 2] += p * vv.z;
                    acc[4 * i + 3] += p * vv.w;
                }
            }
            __syncthreads();
        }
    }

    const float inv = 1.f / l;
    // store to [B, S, H, D]
    float4* orow = (float4*)(g_o + (((size_t)b * SEQ + (size_t)n * 128 + qi) * NH + h) * HD);
#pragma unroll
    for (int i = 0; i < 16; i++) {
        float4 a = ((float4*)acc)[i];
        orow[i] = make_float4(a.x * inv, a.y * inv, a.z * inv, a.w * inv);
    }
}

// ---------------------------------------------------------------------------
// Kernel 3: output projection. o[B,S,H*D] @ Wo[512,512] + bo -> out[B,S,F]
// ---------------------------------------------------------------------------
__global__ void __launch_bounds__(256, 2) oproj_kernel(
    const float* __restrict__ Wo, const float* __restrict__ bo,
    float* __restrict__ Out)
{
    __shared__ float As[BKK][132];
    __shared__ float Bs[BKK][128];

    const int n0 = blockIdx.x * 128;
    const int m0 = blockIdx.y * 128;

    float acc[8][8];
#pragma unroll
    for (int i = 0; i < 8; i++)
#pragma unroll
        for (int j = 0; j < 8; j++) acc[i][j] = 0.f;

    gemm_tile_body(g_o, Wo, m0, n0, acc, As, Bs);

    const int tx = threadIdx.x & 15;
    const int ty = threadIdx.x >> 4;
    const int col = n0 + tx * 8;
    float bb[8];
#pragma unroll
    for (int j = 0; j < 8; j++) bb[j] = bo[col + j];

#pragma unroll
    for (int i = 0; i < 8; i++) {
        int m = m0 + ty * 8 + i;
        float* op = Out + (size_t)m * FD + col;
        float4 v0 = make_float4(acc[i][0] + bb[0], acc[i][1] + bb[1],
                                acc[i][2] + bb[2], acc[i][3] + bb[3]);
        float4 v1 = make_float4(acc[i][4] + bb[4], acc[i][5] + bb[5],
                                acc[i][6] + bb[6], acc[i][7] + bb[7]);
        *(float4*)(op + 0) = v0;
        *(float4*)(op + 4) = v1;
    }
}

// ---------------------------------------------------------------------------
extern "C" void kernel_launch(void* const* d_in, const int* in_sizes, int n_in,
                              void* d_out, int out_size)
{
    const float* inputs_q  = (const float*)d_in[0];
    const float* inputs_kv = (const float*)d_in[1];
    const float* Wq = (const float*)d_in[2];
    const float* bq = (const float*)d_in[3];
    const float* Wk = (const float*)d_in[4];
    const float* bk = (const float*)d_in[5];
    const float* Wv = (const float*)d_in[6];
    const float* bv = (const float*)d_in[7];
    const float* Wo = (const float*)d_in[8];
    const float* bo = (const float*)d_in[9];
    float* out = (float*)d_out;

    dim3 gq(FD / 128, MROWS / 128, 3);
    qkv_kernel<<<gq, 256>>>(inputs_q, inputs_kv, Wq, Wk, Wv, bq, bk, bv);

    dim3 ga(NB, NH, BSZ);
    attn_kernel<<<ga, 128>>>();

    dim3 go(FD / 128, MROWS / 128, 1);
    oproj_kernel<<<go, 256>>>(Wo, bo, out);
}

// round 2
// speedup vs baseline: 1.6184x; 1.6184x over previous
#include <cuda_runtime.h>
#include <cstdint>

// Problem constants
#define BSZ 2
#define SEQ 8192
#define FD  512
#define NH  8
#define HD  64
#define NB  64          // SEQ / 128
#define MROWS (BSZ*SEQ) // 16384

// Scratch (allocation-free rule -> __device__ globals).
__device__ float g_q[(size_t)BSZ*NH*SEQ*HD];
__device__ float g_k[(size_t)BSZ*NH*SEQ*HD];
__device__ float g_v[(size_t)BSZ*NH*SEQ*HD];
__device__ float g_o[(size_t)BSZ*SEQ*NH*HD]; // [B,S,H,D]

#define BK 32

__device__ __forceinline__ unsigned f2tf(float f) {
    unsigned u;
    asm("cvt.rna.tf32.f32 %0, %1;" : "=r"(u) : "f"(f));
    return u;
}

// ---------------------------------------------------------------------------
// tf32 tensor-core GEMM body: C 128x128 tile, BK=32, 256 threads (8 warps).
// Warp w: rows 32*(w&3), cols 64*(w>>2). Per warp: 2 m-frags x 8 n-frags of
// m16n8k8. A staged row-major [128][36] (pad->conflict-free frag loads),
// B staged [32][136].
// ---------------------------------------------------------------------------
__device__ __forceinline__ void gemm_mma_body(
    const float* __restrict__ A, const float* __restrict__ W,
    int m0, int n0, float acc[2][8][4],
    unsigned (*As)[36], unsigned (*Bs)[136])
{
    const int tid  = threadIdx.x;
    const int lane = tid & 31;
    const int warp = tid >> 5;
    const int wm = (warp & 3) * 32;
    const int wn = (warp >> 2) * 64;
    const int g   = lane >> 2;
    const int tig = lane & 3;

    for (int kt = 0; kt < FD; kt += BK) {
        // Stage A tile 128x32 (fp32 -> tf32)
#pragma unroll
        for (int i = 0; i < 4; i++) {
            int id  = i * 256 + tid;
            int row = id >> 3;
            int cg  = (id & 7) << 2;
            float4 a = *(const float4*)(A + (size_t)(m0 + row) * FD + kt + cg);
            *(uint4*)&As[row][cg] =
                make_uint4(f2tf(a.x), f2tf(a.y), f2tf(a.z), f2tf(a.w));
        }
        // Stage B tile 32x128
#pragma unroll
        for (int i = 0; i < 4; i++) {
            int id  = i * 256 + tid;
            int row = id >> 5;
            int c4  = (id & 31) << 2;
            float4 b = *(const float4*)(W + (size_t)(kt + row) * FD + n0 + c4);
            *(uint4*)&Bs[row][c4] =
                make_uint4(f2tf(b.x), f2tf(b.y), f2tf(b.z), f2tf(b.w));
        }
        __syncthreads();

#pragma unroll
        for (int k8 = 0; k8 < BK; k8 += 8) {
            unsigned af[2][4];
#pragma unroll
            for (int mi = 0; mi < 2; mi++) {
                int r = wm + mi * 16 + g;
                af[mi][0] = As[r][k8 + tig];
                af[mi][1] = As[r + 8][k8 + tig];
                af[mi][2] = As[r][k8 + tig + 4];
                af[mi][3] = As[r + 8][k8 + tig + 4];
            }
#pragma unroll
            for (int ni = 0; ni < 8; ni++) {
                unsigned b0 = Bs[k8 + tig][wn + ni * 8 + g];
                unsigned b1 = Bs[k8 + tig + 4][wn + ni * 8 + g];
#pragma unroll
                for (int mi = 0; mi < 2; mi++) {
                    asm volatile(
                        "mma.sync.aligned.m16n8k8.row.col.f32.tf32.tf32.f32 "
                        "{%0,%1,%2,%3}, {%4,%5,%6,%7}, {%8,%9}, {%0,%1,%2,%3};"
                        : "+f"(acc[mi][ni][0]), "+f"(acc[mi][ni][1]),
                          "+f"(acc[mi][ni][2]), "+f"(acc[mi][ni][3])
                        : "r"(af[mi][0]), "r"(af[mi][1]),
                          "r"(af[mi][2]), "r"(af[mi][3]),
                          "r"(b0), "r"(b1));
                }
            }
        }
        __syncthreads();
    }
}

// ---------------------------------------------------------------------------
// Kernel 1: QKV projection (tf32 mma). grid = (4, 128, 3).
// ---------------------------------------------------------------------------
__global__ void __launch_bounds__(256, 2) qkv_kernel(
    const float* __restrict__ Aq, const float* __restrict__ Akv,
    const float* __restrict__ Wq, const float* __restrict__ Wk,
    const float* __restrict__ Wv,
    const float* __restrict__ bq, const float* __restrict__ bk,
    const float* __restrict__ bv)
{
    __shared__ unsigned As[128][36];
    __shared__ unsigned Bs[32][136];

    const int z = blockIdx.z;
    const float* A    = (z == 0) ? Aq : Akv;
    const float* W    = (z == 0) ? Wq : (z == 1 ? Wk : Wv);
    const float* bias = (z == 0) ? bq : (z == 1 ? bk : bv);
    float* O          = (z == 0) ? g_q : (z == 1 ? g_k : g_v);

    const int n0 = blockIdx.x * 128;
    const int m0 = blockIdx.y * 128;

    float acc[2][8][4];
#pragma unroll
    for (int mi = 0; mi < 2; mi++)
#pragma unroll
        for (int ni = 0; ni < 8; ni++)
#pragma unroll
            for (int j = 0; j < 4; j++) acc[mi][ni][j] = 0.f;

    gemm_mma_body(A, W, m0, n0, acc, As, Bs);

    const int lane = threadIdx.x & 31;
    const int warp = threadIdx.x >> 5;
    const int wm = (warp & 3) * 32;
    const int wn = (warp >> 2) * 64;
    const int g   = lane >> 2;
    const int tig = lane & 3;

#pragma unroll
    for (int mi = 0; mi < 2; mi++) {
#pragma unroll
        for (int ni = 0; ni < 8; ni++) {
            int col = n0 + wn + ni * 8 + tig * 2;
            int h  = col >> 6;
            int db = col & 63;
            float2 bb = *(const float2*)(bias + col);
            int row0 = m0 + wm + mi * 16 + g;
            int b = row0 >> 13;
            int s0 = row0 & (SEQ - 1);
            float* base = O + ((size_t)(b * NH + h)) * (SEQ * HD) + db;
            *(float2*)(base + (size_t)s0 * HD) =
                make_float2(acc[mi][ni][0] + bb.x, acc[mi][ni][1] + bb.y);
            *(float2*)(base + (size_t)(s0 + 8) * HD) =
                make_float2(acc[mi][ni][2] + bb.x, acc[mi][ni][3] + bb.y);
        }
    }
}

// ---------------------------------------------------------------------------
// Kernel 2: banded local attention (unchanged fp32 path).
// grid = (NB, NH, BSZ), 128 threads, one query row per thread.
// ---------------------------------------------------------------------------
__global__ void __launch_bounds__(128, 3) attn_kernel()
{
    __shared__ float sK[64 * 64];
    __shared__ float sV[64 * 64];

    const int n = blockIdx.x, h = blockIdx.y, b = blockIdx.z;
    const int qi = threadIdx.x;
    const size_t hb = ((size_t)(b * NH + h)) * SEQ;

    float q[64];
    {
        const float4* qrow = (const float4*)(g_q + (hb + (size_t)n * 128 + qi) * HD);
#pragma unroll
        for (int i = 0; i < 16; i++) ((float4*)q)[i] = qrow[i];
    }
    float acc[64];
#pragma unroll
    for (int i = 0; i < 64; i++) acc[i] = 0.f;
    float l = 0.f;

    for (int kb = 0; kb < 3; kb++) {
        const int kn = n - 1 + kb;
        if (kn < 0 || kn >= NB) continue;
        const size_t kbase = (hb + (size_t)kn * 128) * HD;

        for (int c = 0; c < 2; c++) {
            {
                const int r = qi >> 1;
                const int half = (qi & 1) * 8;
                const float4* kg = (const float4*)(g_k + kbase + (size_t)(c * 64 + r) * HD) + half;
                const float4* vg = (const float4*)(g_v + kbase + (size_t)(c * 64 + r) * HD) + half;
                float4* ks = (float4*)(sK + r * 64) + half;
                float4* vs = (float4*)(sV + r * 64) + half;
#pragma unroll
                for (int i = 0; i < 8; i++) { ks[i] = kg[i]; vs[i] = vg[i]; }
            }
            __syncthreads();

#pragma unroll 2
            for (int jj = 0; jj < 64; jj++) {
                const int j = c * 64 + jj;
                float s0 = 0.f, s1 = 0.f, s2 = 0.f, s3 = 0.f;
                const float4* kj = (const float4*)(sK + jj * 64);
#pragma unroll
                for (int i = 0; i < 16; i++) {
                    float4 kk = kj[i];
                    s0 += q[4 * i + 0] * kk.x;
                    s1 += q[4 * i + 1] * kk.y;
                    s2 += q[4 * i + 2] * kk.z;
                    s3 += q[4 * i + 3] * kk.w;
                }
                const float s = (s0 + s1) + (s2 + s3);
                const bool valid = (kb == 1) || (kb == 0 ? (j >= qi) : (j < qi));
                const float p = valid ? __expf(s * 0.125f) : 0.f;
                l += p;
                const float4* vj = (const float4*)(sV + jj * 64);
#pragma unroll
                for (int i = 0; i < 16; i++) {
                    float4 vv = vj[i];
                    acc[4 * i + 0] += p * vv.x;
                    acc[4 * i + 1] += p * vv.y;
                    acc[4 * i + 2] += p * vv.z;
                    acc[4 * i + 3] += p * vv.w;
                }
            }
            __syncthreads();
        }
    }

    const float inv = 1.f / l;
    float4* orow = (float4*)(g_o + (((size_t)b * SEQ + (size_t)n * 128 + qi) * NH + h) * HD);
#pragma unroll
    for (int i = 0; i < 16; i++) {
        float4 a = ((float4*)acc)[i];
        orow[i] = make_float4(a.x * inv, a.y * inv, a.z * inv, a.w * inv);
    }
}

// ---------------------------------------------------------------------------
// Kernel 3: output projection (tf32 mma). o[B,S,HD*NH] @ Wo + bo -> out.
// ---------------------------------------------------------------------------
__global__ void __launch_bounds__(256, 2) oproj_kernel(
    const float* __restrict__ Wo, const float* __restrict__ bo,
    float* __restrict__ Out)
{
    __shared__ unsigned As[128][36];
    __shared__ unsigned Bs[32][136];

    const int n0 = blockIdx.x * 128;
    const int m0 = blockIdx.y * 128;

    float acc[2][8][4];
#pragma unroll
    for (int mi = 0; mi < 2; mi++)
#pragma unroll
        for (int ni = 0; ni < 8; ni++)
#pragma unroll
            for (int j = 0; j < 4; j++) acc[mi][ni][j] = 0.f;

    gemm_mma_body(g_o, Wo, m0, n0, acc, As, Bs);

    const int lane = threadIdx.x & 31;
    const int warp = threadIdx.x >> 5;
    const int wm = (warp & 3) * 32;
    const int wn = (warp >> 2) * 64;
    const int g   = lane >> 2;
    const int tig = lane & 3;

#pragma unroll
    for (int mi = 0; mi < 2; mi++) {
#pragma unroll
        for (int ni = 0; ni < 8; ni++) {
            int col = n0 + wn + ni * 8 + tig * 2;
            float2 bb = *(const float2*)(bo + col);
            int row0 = m0 + wm + mi * 16 + g;
            *(float2*)(Out + (size_t)row0 * FD + col) =
                make_float2(acc[mi][ni][0] + bb.x, acc[mi][ni][1] + bb.y);
            *(float2*)(Out + (size_t)(row0 + 8) * FD + col) =
                make_float2(acc[mi][ni][2] + bb.x, acc[mi][ni][3] + bb.y);
        }
    }
}

// ---------------------------------------------------------------------------
extern "C" void kernel_launch(void* const* d_in, const int* in_sizes, int n_in,
                              void* d_out, int out_size)
{
    const float* inputs_q  = (const float*)d_in[0];
    const float* inputs_kv = (const float*)d_in[1];
    const float* Wq = (const float*)d_in[2];
    const float* bq = (const float*)d_in[3];
    const float* Wk = (const float*)d_in[4];
    const float* bk = (const float*)d_in[5];
    const float* Wv = (const float*)d_in[6];
    const float* bv = (const float*)d_in[7];
    const float* Wo = (const float*)d_in[8];
    const float* bo = (const float*)d_in[9];
    float* out = (float*)d_out;

    dim3 gq(FD / 128, MROWS / 128, 3);
    qkv_kernel<<<gq, 256>>>(inputs_q, inputs_kv, Wq, Wk, Wv, bq, bk, bv);

    dim3 ga(NB, NH, BSZ);
    attn_kernel<<<ga, 128>>>();

    dim3 go(FD / 128, MROWS / 128, 1);
    oproj_kernel<<<go, 256>>>(Wo, bo, out);
}

// round 3
// speedup vs baseline: 2.7121x; 1.6758x over previous
#include <cuda_runtime.h>
#include <cstdint>

// Problem constants
#define BSZ 2
#define SEQ 8192
#define FD  512
#define NH  8
#define HD  64
#define NB  64          // SEQ / 128
#define MROWS (BSZ*SEQ) // 16384

// Scratch (allocation-free rule -> __device__ globals).
__device__ float g_q[(size_t)BSZ*NH*SEQ*HD];
__device__ float g_k[(size_t)BSZ*NH*SEQ*HD];
__device__ float g_v[(size_t)BSZ*NH*SEQ*HD];
__device__ float g_o[(size_t)BSZ*SEQ*NH*HD]; // [B,S,H,D]

#define BK 32

__device__ __forceinline__ unsigned f2tf(float f) {
    unsigned u;
    asm("cvt.rna.tf32.f32 %0, %1;" : "=r"(u) : "f"(f));
    return u;
}

// ---------------------------------------------------------------------------
// tf32 tensor-core GEMM body: C 128x128 tile, BK=32, 256 threads (8 warps).
// ---------------------------------------------------------------------------
__device__ __forceinline__ void gemm_mma_body(
    const float* __restrict__ A, const float* __restrict__ W,
    int m0, int n0, float acc[2][8][4],
    unsigned (*As)[36], unsigned (*Bs)[136])
{
    const int tid  = threadIdx.x;
    const int lane = tid & 31;
    const int warp = tid >> 5;
    const int wm = (warp & 3) * 32;
    const int wn = (warp >> 2) * 64;
    const int g   = lane >> 2;
    const int tig = lane & 3;

    for (int kt = 0; kt < FD; kt += BK) {
#pragma unroll
        for (int i = 0; i < 4; i++) {
            int id  = i * 256 + tid;
            int row = id >> 3;
            int cg  = (id & 7) << 2;
            float4 a = *(const float4*)(A + (size_t)(m0 + row) * FD + kt + cg);
            *(uint4*)&As[row][cg] =
                make_uint4(f2tf(a.x), f2tf(a.y), f2tf(a.z), f2tf(a.w));
        }
#pragma unroll
        for (int i = 0; i < 4; i++) {
            int id  = i * 256 + tid;
            int row = id >> 5;
            int c4  = (id & 31) << 2;
            float4 b = *(const float4*)(W + (size_t)(kt + row) * FD + n0 + c4);
            *(uint4*)&Bs[row][c4] =
                make_uint4(f2tf(b.x), f2tf(b.y), f2tf(b.z), f2tf(b.w));
        }
        __syncthreads();

#pragma unroll
        for (int k8 = 0; k8 < BK; k8 += 8) {
            unsigned af[2][4];
#pragma unroll
            for (int mi = 0; mi < 2; mi++) {
                int r = wm + mi * 16 + g;
                af[mi][0] = As[r][k8 + tig];
                af[mi][1] = As[r + 8][k8 + tig];
                af[mi][2] = As[r][k8 + tig + 4];
                af[mi][3] = As[r + 8][k8 + tig + 4];
            }
#pragma unroll
            for (int ni = 0; ni < 8; ni++) {
                unsigned b0 = Bs[k8 + tig][wn + ni * 8 + g];
                unsigned b1 = Bs[k8 + tig + 4][wn + ni * 8 + g];
#pragma unroll
                for (int mi = 0; mi < 2; mi++) {
                    asm volatile(
                        "mma.sync.aligned.m16n8k8.row.col.f32.tf32.tf32.f32 "
                        "{%0,%1,%2,%3}, {%4,%5,%6,%7}, {%8,%9}, {%0,%1,%2,%3};"
                        : "+f"(acc[mi][ni][0]), "+f"(acc[mi][ni][1]),
                          "+f"(acc[mi][ni][2]), "+f"(acc[mi][ni][3])
                        : "r"(af[mi][0]), "r"(af[mi][1]),
                          "r"(af[mi][2]), "r"(af[mi][3]),
                          "r"(b0), "r"(b1));
                }
            }
        }
        __syncthreads();
    }
}

// ---------------------------------------------------------------------------
// Kernel 1: QKV projection (tf32 mma). grid = (4, 128, 3).
// ---------------------------------------------------------------------------
__global__ void __launch_bounds__(256, 2) qkv_kernel(
    const float* __restrict__ Aq, const float* __restrict__ Akv,
    const float* __restrict__ Wq, const float* __restrict__ Wk,
    const float* __restrict__ Wv,
    const float* __restrict__ bq, const float* __restrict__ bk,
    const float* __restrict__ bv)
{
    __shared__ unsigned As[128][36];
    __shared__ unsigned Bs[32][136];

    const int z = blockIdx.z;
    const float* A    = (z == 0) ? Aq : Akv;
    const float* W    = (z == 0) ? Wq : (z == 1 ? Wk : Wv);
    const float* bias = (z == 0) ? bq : (z == 1 ? bk : bv);
    float* O          = (z == 0) ? g_q : (z == 1 ? g_k : g_v);

    const int n0 = blockIdx.x * 128;
    const int m0 = blockIdx.y * 128;

    float acc[2][8][4];
#pragma unroll
    for (int mi = 0; mi < 2; mi++)
#pragma unroll
        for (int ni = 0; ni < 8; ni++)
#pragma unroll
            for (int j = 0; j < 4; j++) acc[mi][ni][j] = 0.f;

    gemm_mma_body(A, W, m0, n0, acc, As, Bs);

    const int lane = threadIdx.x & 31;
    const int warp = threadIdx.x >> 5;
    const int wm = (warp & 3) * 32;
    const int wn = (warp >> 2) * 64;
    const int g   = lane >> 2;
    const int tig = lane & 3;

#pragma unroll
    for (int mi = 0; mi < 2; mi++) {
#pragma unroll
        for (int ni = 0; ni < 8; ni++) {
            int col = n0 + wn + ni * 8 + tig * 2;
            int h  = col >> 6;
            int db = col & 63;
            float2 bb = *(const float2*)(bias + col);
            int row0 = m0 + wm + mi * 16 + g;
            int b = row0 >> 13;
            int s0 = row0 & (SEQ - 1);
            float* base = O + ((size_t)(b * NH + h)) * (SEQ * HD) + db;
            *(float2*)(base + (size_t)s0 * HD) =
                make_float2(acc[mi][ni][0] + bb.x, acc[mi][ni][1] + bb.y);
            *(float2*)(base + (size_t)(s0 + 8) * HD) =
                make_float2(acc[mi][ni][2] + bb.x, acc[mi][ni][3] + bb.y);
        }
    }
}

// ---------------------------------------------------------------------------
// Kernel 2: banded local attention, tf32 tensor cores.
// grid = (2*NB, NH, BSZ): blockIdx.x = n*2 + half. 128 threads = 4 warps.
// Each warp owns 16 query rows and ALL keys (no cross-warp reductions).
// Keys processed in 64-key chunks; K/V staged in smem as tf32 with strides
// 68/72 so every mma fragment read is bank-conflict-free.
// P stays in registers: C-fragment -> A-fragment layout via 8 shfls/frag.
// ---------------------------------------------------------------------------
__global__ void __launch_bounds__(128, 3) attn_kernel()
{
    __shared__ unsigned sK[64][68];   // also reused to stage Q (tf32)
    __shared__ unsigned sV[64][72];

    const int n    = blockIdx.x >> 1;
    const int half = blockIdx.x & 1;
    const int h = blockIdx.y, b = blockIdx.z;
    const int tid  = threadIdx.x;
    const int lane = tid & 31;
    const int warp = tid >> 5;
    const int g    = lane >> 2;
    const int tig  = lane & 3;
    const size_t hb = ((size_t)(b * NH + h)) * SEQ;

    // ---- Stage Q tile [64 rows x 64] (tf32) into sK, grab A-fragments ----
    {
        const int r  = tid >> 1;            // 0..63
        const int c0 = (tid & 1) * 32;      // 0 or 32
        const float4* qg = (const float4*)(g_q + (hb + (size_t)(n * 128 + half * 64 + r)) * HD + c0);
#pragma unroll
        for (int i = 0; i < 8; i++) {
            float4 qv = qg[i];
            *(uint4*)&sK[r][c0 + i * 4] =
                make_uint4(f2tf(qv.x), f2tf(qv.y), f2tf(qv.z), f2tf(qv.w));
        }
    }
    __syncthreads();

    unsigned qf[8][4];
    {
        const int r = warp * 16 + g;
#pragma unroll
        for (int kf = 0; kf < 8; kf++) {
            qf[kf][0] = sK[r][kf * 8 + tig];
            qf[kf][1] = sK[r + 8][kf * 8 + tig];
            qf[kf][2] = sK[r][kf * 8 + tig + 4];
            qf[kf][3] = sK[r + 8][kf * 8 + tig + 4];
        }
    }
    __syncthreads();

    float oacc[8][4];
#pragma unroll
    for (int nd = 0; nd < 8; nd++)
#pragma unroll
        for (int e = 0; e < 4; e++) oacc[nd][e] = 0.f;
    float lr0 = 0.f, lr1 = 0.f;

    const int qi0 = half * 64 + warp * 16 + g;   // row-in-block for e0/e1
    // qi1 = qi0 + 8

    for (int c = 0; c < 6; c++) {
        const int kb = c >> 1;
        const int kn = n - 1 + kb;
        if (kn < 0 || kn >= NB) continue;        // uniform across block

        // ---- Load K,V chunk [64 keys x 64] as tf32 ----
        {
            const int r  = tid >> 1;
            const int c0 = (tid & 1) * 32;
            const size_t rowbase = (hb + (size_t)(kn * 128 + (c & 1) * 64 + r)) * HD + c0;
            const float4* kg = (const float4*)(g_k + rowbase);
            const float4* vg = (const float4*)(g_v + rowbase);
#pragma unroll
            for (int i = 0; i < 8; i++) {
                float4 kv = kg[i];
                *(uint4*)&sK[r][c0 + i * 4] =
                    make_uint4(f2tf(kv.x), f2tf(kv.y), f2tf(kv.z), f2tf(kv.w));
                float4 vv = vg[i];
                *(uint4*)&sV[r][c0 + i * 4] =
                    make_uint4(f2tf(vv.x), f2tf(vv.y), f2tf(vv.z), f2tf(vv.w));
            }
        }
        __syncthreads();

        // ---- S = Q K^T over this chunk: per warp [16 x 64] ----
        float acc[8][4];
#pragma unroll
        for (int ni = 0; ni < 8; ni++)
#pragma unroll
            for (int e = 0; e < 4; e++) acc[ni][e] = 0.f;

#pragma unroll
        for (int kf = 0; kf < 8; kf++) {
#pragma unroll
            for (int ni = 0; ni < 8; ni++) {
                unsigned b0 = sK[ni * 8 + g][kf * 8 + tig];
                unsigned b1 = sK[ni * 8 + g][kf * 8 + tig + 4];
                asm volatile(
                    "mma.sync.aligned.m16n8k8.row.col.f32.tf32.tf32.f32 "
                    "{%0,%1,%2,%3}, {%4,%5,%6,%7}, {%8,%9}, {%0,%1,%2,%3};"
                    : "+f"(acc[ni][0]), "+f"(acc[ni][1]),
                      "+f"(acc[ni][2]), "+f"(acc[ni][3])
                    : "r"(qf[kf][0]), "r"(qf[kf][1]),
                      "r"(qf[kf][2]), "r"(qf[kf][3]),
                      "r"(b0), "r"(b1));
            }
        }

        // ---- mask + exp; keep P (tf32 bits) in acc; accumulate row sums ----
        const int jb = (c & 1) * 64;   // chunk key offset within block
#pragma unroll
        for (int ni = 0; ni < 8; ni++) {
            const int j0 = jb + ni * 8 + tig * 2;   // key-in-block for e0/e2
            const int j1 = j0 + 1;
            bool v0, v1, v2, v3;
            if (kb == 1)      { v0 = v1 = v2 = v3 = true; }
            else if (kb == 0) { v0 = j0 >= qi0; v1 = j1 >= qi0;
                                v2 = j0 >= qi0 + 8; v3 = j1 >= qi0 + 8; }
            else              { v0 = j0 < qi0; v1 = j1 < qi0;
                                v2 = j0 < qi0 + 8; v3 = j1 < qi0 + 8; }
            float p0 = v0 ? __expf(acc[ni][0] * 0.125f) : 0.f;
            float p1 = v1 ? __expf(acc[ni][1] * 0.125f) : 0.f;
            float p2 = v2 ? __expf(acc[ni][2] * 0.125f) : 0.f;
            float p3 = v3 ? __expf(acc[ni][3] * 0.125f) : 0.f;
            lr0 += p0 + p1;
            lr1 += p2 + p3;
            acc[ni][0] = __uint_as_float(f2tf(p0));
            acc[ni][1] = __uint_as_float(f2tf(p1));
            acc[ni][2] = __uint_as_float(f2tf(p2));
            acc[ni][3] = __uint_as_float(f2tf(p3));
        }

        // ---- O += P V : convert C-layout P frags to A-layout via shfl ----
        const int s1 = (lane & 28) | (tig >> 1);
        const int s2 = s1 + 2;
        const bool odd = (tig & 1) != 0;
#pragma unroll
        for (int kf = 0; kf < 8; kf++) {
            float t0 = __shfl_sync(0xffffffffu, acc[kf][0], s1);
            float t1 = __shfl_sync(0xffffffffu, acc[kf][1], s1);
            float t2 = __shfl_sync(0xffffffffu, acc[kf][2], s1);
            float t3 = __shfl_sync(0xffffffffu, acc[kf][3], s1);
            float u0 = __shfl_sync(0xffffffffu, acc[kf][0], s2);
            float u1 = __shfl_sync(0xffffffffu, acc[kf][1], s2);
            float u2 = __shfl_sync(0xffffffffu, acc[kf][2], s2);
            float u3 = __shfl_sync(0xffffffffu, acc[kf][3], s2);
            unsigned a0 = __float_as_uint(odd ? t1 : t0);
            unsigned a1 = __float_as_uint(odd ? t3 : t2);
            unsigned a2 = __float_as_uint(odd ? u1 : u0);
            unsigned a3 = __float_as_uint(odd ? u3 : u2);
#pragma unroll
            for (int nd = 0; nd < 8; nd++) {
                unsigned b0 = sV[kf * 8 + tig][nd * 8 + g];
                unsigned b1 = sV[kf * 8 + tig + 4][nd * 8 + g];
                asm volatile(
                    "mma.sync.aligned.m16n8k8.row.col.f32.tf32.tf32.f32 "
                    "{%0,%1,%2,%3}, {%4,%5,%6,%7}, {%8,%9}, {%0,%1,%2,%3};"
                    : "+f"(oacc[nd][0]), "+f"(oacc[nd][1]),
                      "+f"(oacc[nd][2]), "+f"(oacc[nd][3])
                    : "r"(a0), "r"(a1), "r"(a2), "r"(a3),
                      "r"(b0), "r"(b1));
            }
        }
        __syncthreads();
    }

    // ---- finalize: row sums (intra-quad reduce), scale, store ----
    lr0 += __shfl_xor_sync(0xffffffffu, lr0, 1);
    lr0 += __shfl_xor_sync(0xffffffffu, lr0, 2);
    lr1 += __shfl_xor_sync(0xffffffffu, lr1, 1);
    lr1 += __shfl_xor_sync(0xffffffffu, lr1, 2);
    const float inv0 = 1.f / lr0;
    const float inv1 = 1.f / lr1;

    const int row0 = n * 128 + half * 64 + warp * 16 + g;
    float* ob0 = g_o + (((size_t)b * SEQ + row0) * NH + h) * HD;
    float* ob1 = g_o + (((size_t)b * SEQ + row0 + 8) * NH + h) * HD;
#pragma unroll
    for (int nd = 0; nd < 8; nd++) {
        int d = nd * 8 + tig * 2;
        *(float2*)(ob0 + d) = make_float2(oacc[nd][0] * inv0, oacc[nd][1] * inv0);
        *(float2*)(ob1 + d) = make_float2(oacc[nd][2] * inv1, oacc[nd][3] * inv1);
    }
}

// ---------------------------------------------------------------------------
// Kernel 3: output projection (tf32 mma).
// ---------------------------------------------------------------------------
__global__ void __launch_bounds__(256, 2) oproj_kernel(
    const float* __restrict__ Wo, const float* __restrict__ bo,
    float* __restrict__ Out)
{
    __shared__ unsigned As[128][36];
    __shared__ unsigned Bs[32][136];

    const int n0 = blockIdx.x * 128;
    const int m0 = blockIdx.y * 128;

    float acc[2][8][4];
#pragma unroll
    for (int mi = 0; mi < 2; mi++)
#pragma unroll
        for (int ni = 0; ni < 8; ni++)
#pragma unroll
            for (int j = 0; j < 4; j++) acc[mi][ni][j] = 0.f;

    gemm_mma_body(g_o, Wo, m0, n0, acc, As, Bs);

    const int lane = threadIdx.x & 31;
    const int warp = threadIdx.x >> 5;
    const int wm = (warp & 3) * 32;
    const int wn = (warp >> 2) * 64;
    const int g   = lane >> 2;
    const int tig = lane & 3;

#pragma unroll
    for (int mi = 0; mi < 2; mi++) {
#pragma unroll
        for (int ni = 0; ni < 8; ni++) {
            int col = n0 + wn + ni * 8 + tig * 2;
            float2 bb = *(const float2*)(bo + col);
            int row0 = m0 + wm + mi * 16 + g;
            *(float2*)(Out + (size_t)row0 * FD + col) =
                make_float2(acc[mi][ni][0] + bb.x, acc[mi][ni][1] + bb.y);
            *(float2*)(Out + (size_t)(row0 + 8) * FD + col) =
                make_float2(acc[mi][ni][2] + bb.x, acc[mi][ni][3] + bb.y);
        }
    }
}

// ---------------------------------------------------------------------------
extern "C" void kernel_launch(void* const* d_in, const int* in_sizes, int n_in,
                              void* d_out, int out_size)
{
    const float* inputs_q  = (const float*)d_in[0];
    const float* inputs_kv = (const float*)d_in[1];
    const float* Wq = (const float*)d_in[2];
    const float* bq = (const float*)d_in[3];
    const float* Wk = (const float*)d_in[4];
    const float* bk = (const float*)d_in[5];
    const float* Wv = (const float*)d_in[6];
    const float* bv = (const float*)d_in[7];
    const float* Wo = (const float*)d_in[8];
    const float* bo = (const float*)d_in[9];
    float* out = (float*)d_out;

    dim3 gq(FD / 128, MROWS / 128, 3);
    qkv_kernel<<<gq, 256>>>(inputs_q, inputs_kv, Wq, Wk, Wv, bq, bk, bv);

    dim3 ga(NB * 2, NH, BSZ);
    attn_kernel<<<ga, 128>>>();

    dim3 go(FD / 128, MROWS / 128, 1);
    oproj_kernel<<<go, 256>>>(Wo, bo, out);
}

// round 5
// speedup vs baseline: 3.3117x; 1.2211x over previous
#include <cuda_runtime.h>
#include <cstdint>

// Problem constants
#define BSZ 2
#define SEQ 8192
#define FD  512
#define NH  8
#define HD  64
#define NB  64          // SEQ / 128
#define MROWS (BSZ*SEQ) // 16384
#define NT   (FD/32)    // 16 k-tiles

// Scratch (allocation-free rule -> __device__ globals). All tf32-bit uints.
__device__ unsigned g_aq [(size_t)MROWS*FD];     // inputs_q  as tf32
__device__ unsigned g_akv[(size_t)MROWS*FD];     // inputs_kv as tf32
__device__ unsigned g_wq [(size_t)FD*FD];
__device__ unsigned g_wk [(size_t)FD*FD];
__device__ unsigned g_wv [(size_t)FD*FD];
__device__ unsigned g_wo [(size_t)FD*FD];
__device__ unsigned g_q[(size_t)BSZ*NH*SEQ*HD];  // [B,H,S,D] tf32
__device__ unsigned g_k[(size_t)BSZ*NH*SEQ*HD];
__device__ unsigned g_v[(size_t)BSZ*NH*SEQ*HD];
__device__ unsigned g_o[(size_t)BSZ*SEQ*NH*HD];  // [B,S,H,D] tf32

__device__ __forceinline__ unsigned f2tf(float f) {
    unsigned u;
    asm("cvt.rna.tf32.f32 %0, %1;" : "=r"(u) : "f"(f));
    return u;
}
__device__ __forceinline__ unsigned smaddr(const void* p) {
    return (unsigned)__cvta_generic_to_shared(p);
}
#define CP16(dst, src) asm volatile("cp.async.cg.shared.global [%0], [%1], 16;\n" :: "r"(dst), "l"(src))
#define CP_COMMIT()    asm volatile("cp.async.commit_group;\n")
#define CP_WAIT(n)     asm volatile("cp.async.wait_group %0;\n" :: "n"(n))

// ---------------------------------------------------------------------------
// Kernel 0: preconvert fp32 -> tf32 bits (inputs + weights), vectorized x4.
// ---------------------------------------------------------------------------
#define SEG_A  2097152u            // MROWS*FD/4
#define SEG_W  65536u              // FD*FD/4
__global__ void preconvert_kernel(
    const float4* __restrict__ q, const float4* __restrict__ kv,
    const float4* __restrict__ wq, const float4* __restrict__ wk,
    const float4* __restrict__ wv, const float4* __restrict__ wo)
{
    const unsigned total = 2 * SEG_A + 4 * SEG_W;
    for (unsigned i = blockIdx.x * blockDim.x + threadIdx.x; i < total;
         i += gridDim.x * blockDim.x) {
        const float4* src; uint4* dst; unsigned off;
        if (i < SEG_A)                  { src = q;  dst = (uint4*)g_aq;  off = i; }
        else if (i < 2*SEG_A)           { src = kv; dst = (uint4*)g_akv; off = i - SEG_A; }
        else if (i < 2*SEG_A + SEG_W)   { src = wq; dst = (uint4*)g_wq;  off = i - 2*SEG_A; }
        else if (i < 2*SEG_A + 2*SEG_W) { src = wk; dst = (uint4*)g_wk;  off = i - 2*SEG_A - SEG_W; }
        else if (i < 2*SEG_A + 3*SEG_W) { src = wv; dst = (uint4*)g_wv;  off = i - 2*SEG_A - 2*SEG_W; }
        else                            { src = wo; dst = (uint4*)g_wo;  off = i - 2*SEG_A - 3*SEG_W; }
        float4 v = src[off];
        dst[off] = make_uint4(f2tf(v.x), f2tf(v.y), f2tf(v.z), f2tf(v.w));
    }
}

// ---------------------------------------------------------------------------
// 2-stage cp.async tf32 GEMM body. C 128x128 tile, BK=32, 256 threads.
// Dynamic smem: As[2][128][36] then Bs[2][32][136] (uints). 71680 bytes.
// ---------------------------------------------------------------------------
#define A_ST 4608   // 128*36
#define B_ST 4352   // 32*136
#define B_OFF 9216  // 2*A_ST

__device__ __forceinline__ void gemm_issue(
    const unsigned* __restrict__ A, const unsigned* __restrict__ W,
    int m0, int n0, int kt, int s, unsigned* sm)
{
    const int tid = threadIdx.x;
#pragma unroll
    for (int i = 0; i < 4; i++) {
        int id  = i * 256 + tid;
        int row = id >> 3;
        int cg  = (id & 7) << 2;
        CP16(smaddr(sm + s * A_ST + row * 36 + cg),
             A + (size_t)(m0 + row) * FD + kt * 32 + cg);
    }
#pragma unroll
    for (int i = 0; i < 4; i++) {
        int id  = i * 256 + tid;
        int row = id >> 5;
        int c4  = (id & 31) << 2;
        CP16(smaddr(sm + B_OFF + s * B_ST + row * 136 + c4),
             W + (size_t)(kt * 32 + row) * FD + n0 + c4);
    }
    CP_COMMIT();
}

__device__ __forceinline__ void gemm_pipe_body(
    const unsigned* __restrict__ A, const unsigned* __restrict__ W,
    int m0, int n0, float acc[2][8][4], unsigned* sm)
{
    const int lane = threadIdx.x & 31;
    const int warp = threadIdx.x >> 5;
    const int wm = (warp & 3) * 32;
    const int wn = (warp >> 2) * 64;
    const int g   = lane >> 2;
    const int tig = lane & 3;

    gemm_issue(A, W, m0, n0, 0, 0, sm);

    for (int kt = 0; kt < NT; kt++) {
        if (kt + 1 < NT) { gemm_issue(A, W, m0, n0, kt + 1, (kt + 1) & 1, sm); CP_WAIT(1); }
        else             { CP_WAIT(0); }
        __syncthreads();

        const unsigned* As = sm + (kt & 1) * A_ST;
        const unsigned* Bs = sm + B_OFF + (kt & 1) * B_ST;
#pragma unroll
        for (int k8 = 0; k8 < 32; k8 += 8) {
            unsigned af[2][4];
#pragma unroll
            for (int mi = 0; mi < 2; mi++) {
                int r = wm + mi * 16 + g;
                af[mi][0] = As[r * 36 + k8 + tig];
                af[mi][1] = As[(r + 8) * 36 + k8 + tig];
                af[mi][2] = As[r * 36 + k8 + tig + 4];
                af[mi][3] = As[(r + 8) * 36 + k8 + tig + 4];
            }
#pragma unroll
            for (int ni = 0; ni < 8; ni++) {
                unsigned b0 = Bs[(k8 + tig) * 136 + wn + ni * 8 + g];
                unsigned b1 = Bs[(k8 + tig + 4) * 136 + wn + ni * 8 + g];
#pragma unroll
                for (int mi = 0; mi < 2; mi++) {
                    asm volatile(
                        "mma.sync.aligned.m16n8k8.row.col.f32.tf32.tf32.f32 "
                        "{%0,%1,%2,%3}, {%4,%5,%6,%7}, {%8,%9}, {%0,%1,%2,%3};"
                        : "+f"(acc[mi][ni][0]), "+f"(acc[mi][ni][1]),
                          "+f"(acc[mi][ni][2]), "+f"(acc[mi][ni][3])
                        : "r"(af[mi][0]), "r"(af[mi][1]),
                          "r"(af[mi][2]), "r"(af[mi][3]),
                          "r"(b0), "r"(b1));
                }
            }
        }
        __syncthreads();
    }
}

// ---------------------------------------------------------------------------
// Kernel 1: QKV projection. grid = (4, 128, 3). Output tf32 bits, [B,H,S,D].
// ---------------------------------------------------------------------------
__global__ void __launch_bounds__(256, 2) qkv_kernel(
    const float* __restrict__ bq, const float* __restrict__ bk,
    const float* __restrict__ bv)
{
    extern __shared__ unsigned sm[];
    const int z = blockIdx.z;
    const unsigned* A    = (z == 0) ? g_aq : g_akv;
    const unsigned* W    = (z == 0) ? g_wq : (z == 1 ? g_wk : g_wv);
    const float* bias    = (z == 0) ? bq : (z == 1 ? bk : bv);
    unsigned* O          = (z == 0) ? g_q : (z == 1 ? g_k : g_v);

    const int n0 = blockIdx.x * 128;
    const int m0 = blockIdx.y * 128;

    float acc[2][8][4];
#pragma unroll
    for (int mi = 0; mi < 2; mi++)
#pragma unroll
        for (int ni = 0; ni < 8; ni++)
#pragma unroll
            for (int j = 0; j < 4; j++) acc[mi][ni][j] = 0.f;

    gemm_pipe_body(A, W, m0, n0, acc, sm);

    const int lane = threadIdx.x & 31;
    const int warp = threadIdx.x >> 5;
    const int wm = (warp & 3) * 32;
    const int wn = (warp >> 2) * 64;
    const int g   = lane >> 2;
    const int tig = lane & 3;

#pragma unroll
    for (int mi = 0; mi < 2; mi++) {
#pragma unroll
        for (int ni = 0; ni < 8; ni++) {
            int col = n0 + wn + ni * 8 + tig * 2;
            int h  = col >> 6;
            int db = col & 63;
            float2 bb = *(const float2*)(bias + col);
            int row0 = m0 + wm + mi * 16 + g;
            int b = row0 >> 13;
            int s0 = row0 & (SEQ - 1);
            unsigned* base = O + ((size_t)(b * NH + h)) * (SEQ * HD) + db;
            *(uint2*)(base + (size_t)s0 * HD) =
                make_uint2(f2tf(acc[mi][ni][0] + bb.x), f2tf(acc[mi][ni][1] + bb.y));
            *(uint2*)(base + (size_t)(s0 + 8) * HD) =
                make_uint2(f2tf(acc[mi][ni][2] + bb.x), f2tf(acc[mi][ni][3] + bb.y));
        }
    }
}

// ---------------------------------------------------------------------------
// Kernel 2: banded local attention, tf32 mma, cp.async double-buffered chunks.
// grid = (2*NB, NH, BSZ). 128 threads = 4 warps; warp owns 16 query rows.
// Dynamic smem: sK[2][64][68] then sV[2][64][72] (uints). 71680 bytes.
// Fully-masked chunks are skipped (5 of 6 typical).
// ---------------------------------------------------------------------------
#define K_ST 4352   // 64*68
#define V_ST 4608   // 64*72
#define V_OFF 8704  // 2*K_ST

__global__ void __launch_bounds__(128, 3) attn_kernel()
{
    extern __shared__ unsigned sm[];
    unsigned* sKb = sm;
    unsigned* sVb = sm + V_OFF;

    const int n    = blockIdx.x >> 1;
    const int half = blockIdx.x & 1;
    const int h = blockIdx.y, b = blockIdx.z;
    const int tid  = threadIdx.x;
    const int lane = tid & 31;
    const int warp = tid >> 5;
    const int g    = lane >> 2;
    const int tig  = lane & 3;
    const size_t hb = ((size_t)(b * NH + h)) * SEQ;

    // Build uniform valid-chunk list (kb*2 + ch)
    int cl[6]; int L = 0;
#pragma unroll
    for (int kb = 0; kb < 3; kb++) {
        int kn = n - 1 + kb;
        if (kn < 0 || kn >= NB) continue;
#pragma unroll
        for (int ch = 0; ch < 2; ch++) {
            if (kb == 0 && ch == 0 && half == 1) continue;   // all-invalid
            if (kb == 2 && ch == 1 && half == 0) continue;   // all-invalid
            cl[L++] = kb * 2 + ch;
        }
    }

    const int r  = tid >> 1;            // 0..63
    const int co = (tid & 1) * 32;      // uint offset 0/32

    // Issue Q (into sV buf0) and chunk0 (into buf1)
    {
        const unsigned* qg = g_q + (hb + (size_t)(n * 128 + half * 64 + r)) * HD + co;
#pragma unroll
        for (int j = 0; j < 8; j++)
            CP16(smaddr(sVb + r * 72 + co + j * 4), qg + j * 4);
        CP_COMMIT();
    }
    {
        int c = cl[0], kb = c >> 1, ch = c & 1;
        const size_t rowbase = (hb + (size_t)((n - 1 + kb) * 128 + ch * 64 + r)) * HD + co;
#pragma unroll
        for (int j = 0; j < 8; j++) {
            CP16(smaddr(sKb + K_ST + r * 68 + co + j * 4), g_k + rowbase + j * 4);
            CP16(smaddr(sVb + V_ST + r * 72 + co + j * 4), g_v + rowbase + j * 4);
        }
        CP_COMMIT();
    }

    // Extract Q A-fragments
    CP_WAIT(1);
    __syncthreads();
    unsigned qf[8][4];
    {
        const int qr = warp * 16 + g;
#pragma unroll
        for (int kf = 0; kf < 8; kf++) {
            qf[kf][0] = sVb[qr * 72 + kf * 8 + tig];
            qf[kf][1] = sVb[(qr + 8) * 72 + kf * 8 + tig];
            qf[kf][2] = sVb[qr * 72 + kf * 8 + tig + 4];
            qf[kf][3] = sVb[(qr + 8) * 72 + kf * 8 + tig + 4];
        }
    }
    __syncthreads();

    float oacc[8][4];
#pragma unroll
    for (int nd = 0; nd < 8; nd++)
#pragma unroll
        for (int e = 0; e < 4; e++) oacc[nd][e] = 0.f;
    float lr0 = 0.f, lr1 = 0.f;

    const int qi0 = half * 64 + warp * 16 + g;

    for (int i = 0; i < L; i++) {
        // prefetch chunk i+1 into buf (i+2)&1
        if (i + 1 < L) {
            int c = cl[i + 1], kb = c >> 1, ch = c & 1;
            int s = (i + 2) & 1;
            const size_t rowbase = (hb + (size_t)((n - 1 + kb) * 128 + ch * 64 + r)) * HD + co;
#pragma unroll
            for (int j = 0; j < 8; j++) {
                CP16(smaddr(sKb + s * K_ST + r * 68 + co + j * 4), g_k + rowbase + j * 4);
                CP16(smaddr(sVb + s * V_ST + r * 72 + co + j * 4), g_v + rowbase + j * 4);
            }
            CP_COMMIT();
            CP_WAIT(1);
        } else {
            CP_WAIT(0);
        }
        __syncthreads();

        const int s = (i + 1) & 1;
        const unsigned* sK = sKb + s * K_ST;
        const unsigned* sV = sVb + s * V_ST;
        const int c  = cl[i];
        const int kb = c >> 1;
        const int jb = (c & 1) * 64;

        // S = Q K^T : per warp [16 x 64]
        float acc[8][4];
#pragma unroll
        for (int ni = 0; ni < 8; ni++)
#pragma unroll
            for (int e = 0; e < 4; e++) acc[ni][e] = 0.f;

#pragma unroll
        for (int kf = 0; kf < 8; kf++) {
#pragma unroll
            for (int ni = 0; ni < 8; ni++) {
                unsigned b0 = sK[(ni * 8 + g) * 68 + kf * 8 + tig];
                unsigned b1 = sK[(ni * 8 + g) * 68 + kf * 8 + tig + 4];
                asm volatile(
                    "mma.sync.aligned.m16n8k8.row.col.f32.tf32.tf32.f32 "
                    "{%0,%1,%2,%3}, {%4,%5,%6,%7}, {%8,%9}, {%0,%1,%2,%3};"
                    : "+f"(acc[ni][0]), "+f"(acc[ni][1]),
                      "+f"(acc[ni][2]), "+f"(acc[ni][3])
                    : "r"(qf[kf][0]), "r"(qf[kf][1]),
                      "r"(qf[kf][2]), "r"(qf[kf][3]),
                      "r"(b0), "r"(b1));
            }
        }

        // mask + exp, accumulate row sums, re-round P to tf32
#pragma unroll
        for (int ni = 0; ni < 8; ni++) {
            const int j0 = jb + ni * 8 + tig * 2;
            const int j1 = j0 + 1;
            bool v0, v1, v2, v3;
            if (kb == 1)      { v0 = v1 = v2 = v3 = true; }
            else if (kb == 0) { v0 = j0 >= qi0; v1 = j1 >= qi0;
                                v2 = j0 >= qi0 + 8; v3 = j1 >= qi0 + 8; }
            else              { v0 = j0 < qi0; v1 = j1 < qi0;
                                v2 = j0 < qi0 + 8; v3 = j1 < qi0 + 8; }
            float p0 = v0 ? __expf(acc[ni][0] * 0.125f) : 0.f;
            float p1 = v1 ? __expf(acc[ni][1] * 0.125f) : 0.f;
            float p2 = v2 ? __expf(acc[ni][2] * 0.125f) : 0.f;
            float p3 = v3 ? __expf(acc[ni][3] * 0.125f) : 0.f;
            lr0 += p0 + p1;
            lr1 += p2 + p3;
            acc[ni][0] = __uint_as_float(f2tf(p0));
            acc[ni][1] = __uint_as_float(f2tf(p1));
            acc[ni][2] = __uint_as_float(f2tf(p2));
            acc[ni][3] = __uint_as_float(f2tf(p3));
        }

        // O += P V  (C-frag -> A-frag via shfl)
        const int s1 = (lane & 28) | (tig >> 1);
        const int s2 = s1 + 2;
        const bool odd = (tig & 1) != 0;
#pragma unroll
        for (int kf = 0; kf < 8; kf++) {
            float t0 = __shfl_sync(0xffffffffu, acc[kf][0], s1);
            float t1 = __shfl_sync(0xffffffffu, acc[kf][1], s1);
            float t2 = __shfl_sync(0xffffffffu, acc[kf][2], s1);
            float t3 = __shfl_sync(0xffffffffu, acc[kf][3], s1);
            float u0 = __shfl_sync(0xffffffffu, acc[kf][0], s2);
            float u1 = __shfl_sync(0xffffffffu, acc[kf][1], s2);
            float u2 = __shfl_sync(0xffffffffu, acc[kf][2], s2);
            float u3 = __shfl_sync(0xffffffffu, acc[kf][3], s2);
            unsigned a0 = __float_as_uint(odd ? t1 : t0);
            unsigned a1 = __float_as_uint(odd ? t3 : t2);
            unsigned a2 = __float_as_uint(odd ? u1 : u0);
            unsigned a3 = __float_as_uint(odd ? u3 : u2);
#pragma unroll
            for (int nd = 0; nd < 8; nd++) {
                unsigned b0 = sV[(kf * 8 + tig) * 72 + nd * 8 + g];
                unsigned b1 = sV[(kf * 8 + tig + 4) * 72 + nd * 8 + g];
                asm volatile(
                    "mma.sync.aligned.m16n8k8.row.col.f32.tf32.tf32.f32 "
                    "{%0,%1,%2,%3}, {%4,%5,%6,%7}, {%8,%9}, {%0,%1,%2,%3};"
                    : "+f"(oacc[nd][0]), "+f"(oacc[nd][1]),
                      "+f"(oacc[nd][2]), "+f"(oacc[nd][3])
                    : "r"(a0), "r"(a1), "r"(a2), "r"(a3),
                      "r"(b0), "r"(b1));
            }
        }
        __syncthreads();
    }

    // finalize
    lr0 += __shfl_xor_sync(0xffffffffu, lr0, 1);
    lr0 += __shfl_xor_sync(0xffffffffu, lr0, 2);
    lr1 += __shfl_xor_sync(0xffffffffu, lr1, 1);
    lr1 += __shfl_xor_sync(0xffffffffu, lr1, 2);
    const float inv0 = 1.f / lr0;
    const float inv1 = 1.f / lr1;

    const int row0 = n * 128 + half * 64 + warp * 16 + g;
    unsigned* ob0 = g_o + (((size_t)b * SEQ + row0) * NH + h) * HD;
    unsigned* ob1 = g_o + (((size_t)b * SEQ + row0 + 8) * NH + h) * HD;
#pragma unroll
    for (int nd = 0; nd < 8; nd++) {
        int d = nd * 8 + tig * 2;
        *(uint2*)(ob0 + d) = make_uint2(f2tf(oacc[nd][0] * inv0), f2tf(oacc[nd][1] * inv0));
        *(uint2*)(ob1 + d) = make_uint2(f2tf(oacc[nd][2] * inv1), f2tf(oacc[nd][3] * inv1));
    }
}

// ---------------------------------------------------------------------------
// Kernel 3: output projection. g_o(tf32) @ g_wo + bo -> out (fp32).
// ---------------------------------------------------------------------------
__global__ void __launch_bounds__(256, 2) oproj_kernel(
    const float* __restrict__ bo, float* __restrict__ Out)
{
    extern __shared__ unsigned sm[];
    const int n0 = blockIdx.x * 128;
    const int m0 = blockIdx.y * 128;

    float acc[2][8][4];
#pragma unroll
    for (int mi = 0; mi < 2; mi++)
#pragma unroll
        for (int ni = 0; ni < 8; ni++)
#pragma unroll
            for (int j = 0; j < 4; j++) acc[mi][ni][j] = 0.f;

    gemm_pipe_body(g_o, g_wo, m0, n0, acc, sm);

    const int lane = threadIdx.x & 31;
    const int warp = threadIdx.x >> 5;
    const int wm = (warp & 3) * 32;
    const int wn = (warp >> 2) * 64;
    const int g   = lane >> 2;
    const int tig = lane & 3;

#pragma unroll
    for (int mi = 0; mi < 2; mi++) {
#pragma unroll
        for (int ni = 0; ni < 8; ni++) {
            int col = n0 + wn + ni * 8 + tig * 2;
            float2 bb = *(const float2*)(bo + col);
            int row0 = m0 + wm + mi * 16 + g;
            *(float2*)(Out + (size_t)row0 * FD + col) =
                make_float2(acc[mi][ni][0] + bb.x, acc[mi][ni][1] + bb.y);
            *(float2*)(Out + (size_t)(row0 + 8) * FD + col) =
                make_float2(acc[mi][ni][2] + bb.x, acc[mi][ni][3] + bb.y);
        }
    }
}

// ---------------------------------------------------------------------------
extern "C" void kernel_launch(void* const* d_in, const int* in_sizes, int n_in,
                              void* d_out, int out_size)
{
    const float* inputs_q  = (const float*)d_in[0];
    const float* inputs_kv = (const float*)d_in[1];
    const float* Wq = (const float*)d_in[2];
    const float* bq = (const float*)d_in[3];
    const float* Wk = (const float*)d_in[4];
    const float* bk = (const float*)d_in[5];
    const float* Wv = (const float*)d_in[6];
    const float* bv = (const float*)d_in[7];
    const float* Wo = (const float*)d_in[8];
    const float* bo = (const float*)d_in[9];
    float* out = (float*)d_out;

    // Idempotent, deterministic, host-side; called every time (no static state).
    cudaFuncSetAttribute(qkv_kernel,   cudaFuncAttributeMaxDynamicSharedMemorySize, 71680);
    cudaFuncSetAttribute(attn_kernel,  cudaFuncAttributeMaxDynamicSharedMemorySize, 71680);
    cudaFuncSetAttribute(oproj_kernel, cudaFuncAttributeMaxDynamicSharedMemorySize, 71680);

    preconvert_kernel<<<2048, 256>>>(
        (const float4*)inputs_q, (const float4*)inputs_kv,
        (const float4*)Wq, (const float4*)Wk,
        (const float4*)Wv, (const float4*)Wo);

    dim3 gq(FD / 128, MROWS / 128, 3);
    qkv_kernel<<<gq, 256, 71680>>>(bq, bk, bv);

    dim3 ga(NB * 2, NH, BSZ);
    attn_kernel<<<ga, 128, 71680>>>();

    dim3 go(FD / 128, MROWS / 128, 1);
    oproj_kernel<<<go, 256, 71680>>>(bo, out);
}

// round 7
// speedup vs baseline: 6.5441x; 1.9761x over previous
#include <cuda_runtime.h>
#include <cuda_fp16.h>
#include <cstdint>

// Problem constants
#define BSZ 2
#define SEQ 8192
#define FD  512
#define NH  8
#define HD  64
#define NB  64          // SEQ / 128
#define MROWS (BSZ*SEQ) // 16384
#define NTK  8          // k-tiles of 64 over FD

// Scratch (allocation-free rule -> __device__ globals). fp16 everywhere.
__device__ __half g_aq [(size_t)MROWS*FD];     // inputs_q  fp16
__device__ __half g_akv[(size_t)MROWS*FD];     // inputs_kv fp16
__device__ __half g_wq [(size_t)FD*FD];        // W transposed [n][k] fp16
__device__ __half g_wk [(size_t)FD*FD];
__device__ __half g_wv [(size_t)FD*FD];
__device__ __half g_wo [(size_t)FD*FD];
__device__ __half g_q[(size_t)BSZ*NH*SEQ*HD];  // [B,H,S,D]
__device__ __half g_k[(size_t)BSZ*NH*SEQ*HD];
__device__ __half g_v[(size_t)BSZ*NH*SEQ*HD];
__device__ __half g_o[(size_t)BSZ*SEQ*NH*HD];  // [B,S,H,D]

__device__ __forceinline__ unsigned smaddr(const void* p) {
    return (unsigned)__cvta_generic_to_shared(p);
}
__device__ __forceinline__ unsigned packh2(float lo, float hi) {
    unsigned r;
    asm("cvt.rn.f16x2.f32 %0, %1, %2;" : "=r"(r) : "f"(hi), "f"(lo));
    return r;
}
#define CP16(dst, src) asm volatile("cp.async.cg.shared.global [%0], [%1], 16;\n" :: "r"(dst), "l"(src))
#define CP_COMMIT()    asm volatile("cp.async.commit_group;\n")
#define CP_WAIT(n)     asm volatile("cp.async.wait_group %0;\n" :: "n"(n))

#define LDSM4(r0,r1,r2,r3,a) \
    asm volatile("ldmatrix.sync.aligned.m8n8.x4.shared.b16 {%0,%1,%2,%3}, [%4];" \
                 : "=r"(r0), "=r"(r1), "=r"(r2), "=r"(r3) : "r"(a))
#define LDSM4T(r0,r1,r2,r3,a) \
    asm volatile("ldmatrix.sync.aligned.m8n8.x4.trans.shared.b16 {%0,%1,%2,%3}, [%4];" \
                 : "=r"(r0), "=r"(r1), "=r"(r2), "=r"(r3) : "r"(a))
#define MMA16816(c, a0,a1,a2,a3, b0,b1) \
    asm volatile("mma.sync.aligned.m16n8k16.row.col.f32.f16.f16.f32 " \
                 "{%0,%1,%2,%3}, {%4,%5,%6,%7}, {%8,%9}, {%0,%1,%2,%3};" \
                 : "+f"((c)[0]), "+f"((c)[1]), "+f"((c)[2]), "+f"((c)[3]) \
                 : "r"(a0), "r"(a1), "r"(a2), "r"(a3), "r"(b0), "r"(b1))

// ---------------------------------------------------------------------------
// Kernel 0a: activations fp32 -> fp16.
// ---------------------------------------------------------------------------
#define SEG_A 2097152u             // MROWS*FD/4
__global__ void preact_kernel(const float4* __restrict__ q,
                              const float4* __restrict__ kv)
{
    for (unsigned i = blockIdx.x * blockDim.x + threadIdx.x; i < 2 * SEG_A;
         i += gridDim.x * blockDim.x) {
        const float4* src = (i < SEG_A) ? q : kv;
        uint2* dst = (i < SEG_A) ? (uint2*)g_aq : (uint2*)g_akv;
        unsigned off = (i < SEG_A) ? i : i - SEG_A;
        float4 v = src[off];
        dst[off] = make_uint2(packh2(v.x, v.y), packh2(v.z, v.w));
    }
}

// ---------------------------------------------------------------------------
// Kernel 0b: weight transpose + convert: dst[n][k] = fp16(src[k][n]).
// ---------------------------------------------------------------------------
__global__ void wtrans_kernel(const float* __restrict__ wq,
                              const float* __restrict__ wk,
                              const float* __restrict__ wv,
                              const float* __restrict__ wo)
{
    __shared__ float t[32][33];
    const int z = blockIdx.z;
    const float* src = (z == 0) ? wq : (z == 1 ? wk : (z == 2 ? wv : wo));
    __half* dst      = (z == 0) ? g_wq : (z == 1 ? g_wk : (z == 2 ? g_wv : g_wo));
    const int bk = blockIdx.x * 32;
    const int bn = blockIdx.y * 32;
    const int tx = threadIdx.x & 31;
    const int ty = threadIdx.x >> 5;
#pragma unroll
    for (int i = 0; i < 4; i++) {
        int k = ty + i * 8;
        t[k][tx] = src[(size_t)(bk + k) * FD + bn + tx];
    }
    __syncthreads();
#pragma unroll
    for (int i = 0; i < 4; i++) {
        int n = ty + i * 8;
        dst[(size_t)(bn + n) * FD + bk + tx] = __float2half_rn(t[tx][n]);
    }
}

// ---------------------------------------------------------------------------
// fp16 GEMM body: C 128x128 tile, BK=64, 256 threads (8 warps).
// Smem: A[2][128 rows x 128B] @ 0, B[2][...] @ 32768. SW128 XOR swizzle.
// Per warp: 2 m16-frags x 8 n8-frags. cp.async double buffered.
// ---------------------------------------------------------------------------
#define GA(buf) ((buf) * 16384u)
#define GB(buf) (32768u + (buf) * 16384u)
#define GEMM_SMEM 65536

__device__ __forceinline__ void gemm_issue16(
    const __half* __restrict__ A, const __half* __restrict__ Bt,
    int m0, int n0, int kt, int buf, unsigned sbase)
{
    const int tid = threadIdx.x;
    const unsigned ab = sbase + GA(buf);
    const unsigned bb = sbase + GB(buf);
#pragma unroll
    for (int i = 0; i < 4; i++) {
        int u = i * 256 + tid;             // 1024 units: 128 rows x 8
        int row = u >> 3, un = u & 7;
        unsigned sw = (unsigned)(row * 128) + ((un * 16) ^ ((row & 7) << 4));
        CP16(ab + sw, A  + (size_t)(m0 + row) * FD + kt * 64 + un * 8);
        CP16(bb + sw, Bt + (size_t)(n0 + row) * FD + kt * 64 + un * 8);
    }
    CP_COMMIT();
}

__device__ __forceinline__ void gemm16_body(
    const __half* __restrict__ A, const __half* __restrict__ Bt,
    int m0, int n0, float acc[2][8][4], char* smem)
{
    const int lane = threadIdx.x & 31;
    const int warp = threadIdx.x >> 5;
    const int wm = (warp & 3) * 32;
    const int wn = (warp >> 2) * 64;
    const unsigned sbase = smaddr(smem);
    const int l15 = lane & 15;
    const int hb16 = (lane & 16) ? 16 : 0;

    gemm_issue16(A, Bt, m0, n0, 0, 0, sbase);
    gemm_issue16(A, Bt, m0, n0, 1, 1, sbase);

    for (int kt = 0; kt < NTK; kt++) {
        const int buf = kt & 1;
        if (kt + 2 < NTK) { CP_WAIT(1); }
        else              { CP_WAIT(0); }
        __syncthreads();

        const unsigned ab = sbase + GA(buf);
        const unsigned bb = sbase + GB(buf);
#pragma unroll
        for (int kk = 0; kk < 4; kk++) {
            const int bcol = kk * 32 + hb16;
            unsigned af[2][4];
#pragma unroll
            for (int mi = 0; mi < 2; mi++) {
                int row = wm + mi * 16 + l15;
                unsigned ad = ab + row * 128 + (bcol ^ ((row & 7) << 4));
                LDSM4(af[mi][0], af[mi][1], af[mi][2], af[mi][3], ad);
            }
#pragma unroll
            for (int np = 0; np < 4; np++) {
                int row = wn + np * 16 + l15;
                unsigned bd = bb + row * 128 + (bcol ^ ((row & 7) << 4));
                unsigned r0, r1, r2, r3;
                LDSM4(r0, r1, r2, r3, bd);
#pragma unroll
                for (int mi = 0; mi < 2; mi++) {
                    MMA16816(acc[mi][2 * np],     af[mi][0], af[mi][1], af[mi][2], af[mi][3], r0, r2);
                    MMA16816(acc[mi][2 * np + 1], af[mi][0], af[mi][1], af[mi][2], af[mi][3], r1, r3);
                }
            }
        }
        __syncthreads();
        if (kt + 2 < NTK)
            gemm_issue16(A, Bt, m0, n0, kt + 2, buf, sbase);
    }
}

// ---------------------------------------------------------------------------
// Kernel 1: QKV projection. grid = (4, 128, 3). Output fp16 [B,H,S,D].
// ---------------------------------------------------------------------------
__global__ void __launch_bounds__(256, 2) qkv_kernel(
    const float* __restrict__ bq, const float* __restrict__ bk,
    const float* __restrict__ bv)
{
    extern __shared__ char smem[];
    const int z = blockIdx.z;
    const __half* A  = (z == 0) ? g_aq : g_akv;
    const __half* Bt = (z == 0) ? g_wq : (z == 1 ? g_wk : g_wv);
    const float* bias = (z == 0) ? bq : (z == 1 ? bk : bv);
    __half* O        = (z == 0) ? g_q : (z == 1 ? g_k : g_v);

    const int n0 = blockIdx.x * 128;
    const int m0 = blockIdx.y * 128;

    float acc[2][8][4];
#pragma unroll
    for (int mi = 0; mi < 2; mi++)
#pragma unroll
        for (int ni = 0; ni < 8; ni++)
#pragma unroll
            for (int j = 0; j < 4; j++) acc[mi][ni][j] = 0.f;

    gemm16_body(A, Bt, m0, n0, acc, smem);

    const int lane = threadIdx.x & 31;
    const int warp = threadIdx.x >> 5;
    const int wm = (warp & 3) * 32;
    const int wn = (warp >> 2) * 64;
    const int g   = lane >> 2;
    const int tig = lane & 3;

#pragma unroll
    for (int mi = 0; mi < 2; mi++) {
#pragma unroll
        for (int ni = 0; ni < 8; ni++) {
            int col = n0 + wn + ni * 8 + tig * 2;
            int h  = col >> 6;
            int db = col & 63;
            float2 bb = *(const float2*)(bias + col);
            int row0 = m0 + wm + mi * 16 + g;
            int b = row0 >> 13;
            int s0 = row0 & (SEQ - 1);
            __half* base = O + ((size_t)(b * NH + h)) * (SEQ * HD) + db;
            *(unsigned*)(base + (size_t)s0 * HD) =
                packh2(acc[mi][ni][0] + bb.x, acc[mi][ni][1] + bb.y);
            *(unsigned*)(base + (size_t)(s0 + 8) * HD) =
                packh2(acc[mi][ni][2] + bb.x, acc[mi][ni][3] + bb.y);
        }
    }
}

// ---------------------------------------------------------------------------
// Kernel 3: output projection. g_o[B,S,512] @ Wo^T + bo -> out fp32.
// ---------------------------------------------------------------------------
__global__ void __launch_bounds__(256, 2) oproj_kernel(
    const float* __restrict__ bo, float* __restrict__ Out)
{
    extern __shared__ char smem[];
    const int n0 = blockIdx.x * 128;
    const int m0 = blockIdx.y * 128;

    float acc[2][8][4];
#pragma unroll
    for (int mi = 0; mi < 2; mi++)
#pragma unroll
        for (int ni = 0; ni < 8; ni++)
#pragma unroll
            for (int j = 0; j < 4; j++) acc[mi][ni][j] = 0.f;

    gemm16_body(g_o, g_wo, m0, n0, acc, smem);

    const int lane = threadIdx.x & 31;
    const int warp = threadIdx.x >> 5;
    const int wm = (warp & 3) * 32;
    const int wn = (warp >> 2) * 64;
    const int g   = lane >> 2;
    const int tig = lane & 3;

#pragma unroll
    for (int mi = 0; mi < 2; mi++) {
#pragma unroll
        for (int ni = 0; ni < 8; ni++) {
            int col = n0 + wn + ni * 8 + tig * 2;
            float2 bb = *(const float2*)(bo + col);
            int row0 = m0 + wm + mi * 16 + g;
            *(float2*)(Out + (size_t)row0 * FD + col) =
                make_float2(acc[mi][ni][0] + bb.x, acc[mi][ni][1] + bb.y);
            *(float2*)(Out + (size_t)(row0 + 8) * FD + col) =
                make_float2(acc[mi][ni][2] + bb.x, acc[mi][ni][3] + bb.y);
        }
    }
}

// ---------------------------------------------------------------------------
// Kernel 2: banded local attention, fp16 mma + ldmatrix.
// grid = (2*NB, NH, BSZ). 128 threads = 4 warps; warp owns 16 query rows.
// Smem: Q[64x128B] @ 0, K[2][64x128B] @ 8192, V[2][64x128B] @ 24576.
// P stays in registers; fp16 A-frag = packed QK C-frag (no shuffles).
// ---------------------------------------------------------------------------
#define AQ_OFF 0u
#define AK_OFF(buf) (8192u + (buf) * 8192u)
#define AV_OFF(buf) (24576u + (buf) * 8192u)
#define ATTN_SMEM 40960

__global__ void __launch_bounds__(128, 3) attn_kernel()
{
    extern __shared__ char smem[];
    const unsigned sbase = smaddr(smem);

    const int n    = blockIdx.x >> 1;
    const int half = blockIdx.x & 1;
    const int h = blockIdx.y, b = blockIdx.z;
    const int tid  = threadIdx.x;
    const int lane = tid & 31;
    const int warp = tid >> 5;
    const int g    = lane >> 2;
    const int tig  = lane & 3;
    const int l15  = lane & 15;
    const int hb16 = (lane & 16) ? 16 : 0;
    const size_t hb = ((size_t)(b * NH + h)) * SEQ;

    // Valid-chunk list (uniform across CTA)
    int cl[6]; int L = 0;
#pragma unroll
    for (int kb = 0; kb < 3; kb++) {
        int kn = n - 1 + kb;
        if (kn < 0 || kn >= NB) continue;
#pragma unroll
        for (int ch = 0; ch < 2; ch++) {
            if (kb == 0 && ch == 0 && half == 1) continue;
            if (kb == 2 && ch == 1 && half == 0) continue;
            cl[L++] = kb * 2 + ch;
        }
    }

    // Stage Q tile [64 x 64 halves] swizzled (group A), then chunk0 (group B)
#pragma unroll
    for (int i = 0; i < 4; i++) {
        int u = i * 128 + tid;             // 512 units
        int row = u >> 3, un = u & 7;
        unsigned sw = (unsigned)(row * 128) + ((un * 16) ^ ((row & 7) << 4));
        CP16(sbase + AQ_OFF + sw,
             g_q + (hb + (size_t)(n * 128 + half * 64 + row)) * HD + un * 8);
    }
    CP_COMMIT();
    {
        int c = cl[0], kb = c >> 1, ch = c & 1;
        const size_t rb = (hb + (size_t)((n - 1 + kb) * 128 + ch * 64)) * HD;
#pragma unroll
        for (int i = 0; i < 4; i++) {
            int u = i * 128 + tid;
            int row = u >> 3, un = u & 7;
            unsigned sw = (unsigned)(row * 128) + ((un * 16) ^ ((row & 7) << 4));
            CP16(sbase + AK_OFF(1) + sw, g_k + rb + (size_t)row * HD + un * 8);
            CP16(sbase + AV_OFF(1) + sw, g_v + rb + (size_t)row * HD + un * 8);
        }
        CP_COMMIT();
    }

    // Q fragments (4 k16 frags)
    CP_WAIT(1);
    __syncthreads();
    unsigned qf[4][4];
    {
        const int row = warp * 16 + l15;
        const unsigned rbase = sbase + AQ_OFF + row * 128;
        const unsigned xr = (row & 7) << 4;
#pragma unroll
        for (int kk = 0; kk < 4; kk++) {
            unsigned ad = rbase + ((unsigned)(kk * 32 + hb16) ^ xr);
            LDSM4(qf[kk][0], qf[kk][1], qf[kk][2], qf[kk][3], ad);
        }
    }

    float oacc[8][4];
#pragma unroll
    for (int nd = 0; nd < 8; nd++)
#pragma unroll
        for (int e = 0; e < 4; e++) oacc[nd][e] = 0.f;
    float lr0 = 0.f, lr1 = 0.f;

    const int qi0 = half * 64 + warp * 16 + g;

    for (int i = 0; i < L; i++) {
        if (i + 1 < L) {
            int c = cl[i + 1], kb = c >> 1, ch = c & 1;
            int s = (i + 2) & 1;
            const size_t rb = (hb + (size_t)((n - 1 + kb) * 128 + ch * 64)) * HD;
#pragma unroll
            for (int j = 0; j < 4; j++) {
                int u = j * 128 + tid;
                int row = u >> 3, un = u & 7;
                unsigned sw = (unsigned)(row * 128) + ((un * 16) ^ ((row & 7) << 4));
                CP16(sbase + AK_OFF(s) + sw, g_k + rb + (size_t)row * HD + un * 8);
                CP16(sbase + AV_OFF(s) + sw, g_v + rb + (size_t)row * HD + un * 8);
            }
            CP_COMMIT();
            CP_WAIT(1);
        } else {
            CP_WAIT(0);
        }
        __syncthreads();

        const int s = (i + 1) & 1;
        const unsigned kbs = sbase + AK_OFF(s);
        const unsigned vbs = sbase + AV_OFF(s);
        const int c  = cl[i];
        const int kb = c >> 1;
        const int jb = (c & 1) * 64;

        // S = Q K^T : per warp [16 x 64]
        float acc[8][4];
#pragma unroll
        for (int ni = 0; ni < 8; ni++)
#pragma unroll
            for (int e = 0; e < 4; e++) acc[ni][e] = 0.f;

#pragma unroll
        for (int kk = 0; kk < 4; kk++) {
            const int bcol = kk * 32 + hb16;
#pragma unroll
            for (int jp = 0; jp < 4; jp++) {
                int row = jp * 16 + l15;
                unsigned bd = kbs + row * 128 + ((unsigned)bcol ^ ((row & 7) << 4));
                unsigned r0, r1, r2, r3;
                LDSM4(r0, r1, r2, r3, bd);
                MMA16816(acc[2 * jp],     qf[kk][0], qf[kk][1], qf[kk][2], qf[kk][3], r0, r2);
                MMA16816(acc[2 * jp + 1], qf[kk][0], qf[kk][1], qf[kk][2], qf[kk][3], r1, r3);
            }
        }

        // mask + exp; keep P as fp32 in acc; accumulate row sums
#pragma unroll
        for (int ni = 0; ni < 8; ni++) {
            const int j0 = jb + ni * 8 + tig * 2;
            const int j1 = j0 + 1;
            bool v0, v1, v2, v3;
            if (kb == 1)      { v0 = v1 = v2 = v3 = true; }
            else if (kb == 0) { v0 = j0 >= qi0; v1 = j1 >= qi0;
                                v2 = j0 >= qi0 + 8; v3 = j1 >= qi0 + 8; }
            else              { v0 = j0 < qi0; v1 = j1 < qi0;
                                v2 = j0 < qi0 + 8; v3 = j1 < qi0 + 8; }
            float p0 = v0 ? __expf(acc[ni][0] * 0.125f) : 0.f;
            float p1 = v1 ? __expf(acc[ni][1] * 0.125f) : 0.f;
            float p2 = v2 ? __expf(acc[ni][2] * 0.125f) : 0.f;
            float p3 = v3 ? __expf(acc[ni][3] * 0.125f) : 0.f;
            lr0 += p0 + p1;
            lr1 += p2 + p3;
            acc[ni][0] = p0; acc[ni][1] = p1; acc[ni][2] = p2; acc[ni][3] = p3;
        }

        // O += P V : A-frag = packed C-frag (no shuffles); V via ldmatrix.trans
#pragma unroll
        for (int jk = 0; jk < 4; jk++) {
            unsigned a0 = packh2(acc[2 * jk][0],     acc[2 * jk][1]);
            unsigned a1 = packh2(acc[2 * jk][2],     acc[2 * jk][3]);
            unsigned a2 = packh2(acc[2 * jk + 1][0], acc[2 * jk + 1][1]);
            unsigned a3 = packh2(acc[2 * jk + 1][2], acc[2 * jk + 1][3]);
#pragma unroll
            for (int np = 0; np < 4; np++) {
                int row = jk * 16 + l15;
                unsigned bd = vbs + row * 128 +
                              ((unsigned)(np * 32 + hb16) ^ ((row & 7) << 4));
                unsigned r0, r1, r2, r3;
                LDSM4T(r0, r1, r2, r3, bd);
                MMA16816(oacc[2 * np],     a0, a1, a2, a3, r0, r1);
                MMA16816(oacc[2 * np + 1], a0, a1, a2, a3, r2, r3);
            }
        }
        __syncthreads();
    }

    // finalize: intra-quad row sums, scale, store fp16
    lr0 += __shfl_xor_sync(0xffffffffu, lr0, 1);
    lr0 += __shfl_xor_sync(0xffffffffu, lr0, 2);
    lr1 += __shfl_xor_sync(0xffffffffu, lr1, 1);
    lr1 += __shfl_xor_sync(0xffffffffu, lr1, 2);
    const float inv0 = 1.f / lr0;
    const float inv1 = 1.f / lr1;

    const int row0 = n * 128 + half * 64 + warp * 16 + g;
    __half* ob0 = g_o + (((size_t)b * SEQ + row0) * NH + h) * HD;
    __half* ob1 = g_o + (((size_t)b * SEQ + row0 + 8) * NH + h) * HD;
#pragma unroll
    for (int nd = 0; nd < 8; nd++) {
        int d = nd * 8 + tig * 2;
        *(unsigned*)(ob0 + d) = packh2(oacc[nd][0] * inv0, oacc[nd][1] * inv0);
        *(unsigned*)(ob1 + d) = packh2(oacc[nd][2] * inv1, oacc[nd][3] * inv1);
    }
}

// ---------------------------------------------------------------------------
extern "C" void kernel_launch(void* const* d_in, const int* in_sizes, int n_in,
                              void* d_out, int out_size)
{
    const float* inputs_q  = (const float*)d_in[0];
    const float* inputs_kv = (const float*)d_in[1];
    const float* Wq = (const float*)d_in[2];
    const float* bq = (const float*)d_in[3];
    const float* Wk = (const float*)d_in[4];
    const float* bk = (const float*)d_in[5];
    const float* Wv = (const float*)d_in[6];
    const float* bv = (const float*)d_in[7];
    const float* Wo = (const float*)d_in[8];
    const float* bo = (const float*)d_in[9];
    float* out = (float*)d_out;

    // Idempotent host-side calls, executed every invocation (no static state).
    cudaFuncSetAttribute(qkv_kernel,   cudaFuncAttributeMaxDynamicSharedMemorySize, GEMM_SMEM);
    cudaFuncSetAttribute(oproj_kernel, cudaFuncAttributeMaxDynamicSharedMemorySize, GEMM_SMEM);
    cudaFuncSetAttribute(attn_kernel,  cudaFuncAttributeMaxDynamicSharedMemorySize, ATTN_SMEM);

    preact_kernel<<<1024, 256>>>((const float4*)inputs_q, (const float4*)inputs_kv);
    wtrans_kernel<<<dim3(16, 16, 4), 256>>>(Wq, Wk, Wv, Wo);

    dim3 gq(FD / 128, MROWS / 128, 3);
    qkv_kernel<<<gq, 256, GEMM_SMEM>>>(bq, bk, bv);

    dim3 ga(NB * 2, NH, BSZ);
    attn_kernel<<<ga, 128, ATTN_SMEM>>>();

    dim3 go(FD / 128, MROWS / 128, 1);
    oproj_kernel<<<go, 256, GEMM_SMEM>>>(bo, out);
}